// round 15
// baseline (speedup 1.0000x reference)
#include <cuda_runtime.h>
#include <math.h>

#define NN 2048
#define DD 256
#define HH 128
#define GG 8
#define MAXD 128
#define NWRD 64     // 32-bit words per adjacency row (2048 bits)
#define TCAP 32     // max triangle pairs per node (padded build buffer)
#define TMAX 8192   // max total compacted triangle pairs

// ---------------- device scratch (static, no runtime allocation) ----------------
static __device__ unsigned g_adj[NN*NWRD];
static __device__ int      g_deg[NN];
static __device__ int      g_nbr[NN*MAXD];
static __device__ int      g_off[NN+1];
static __device__ int      g_nedges;
static __device__ unsigned short g_ecol[32768];   // CSR columns (u16)
static __device__ int      g_tricnt[NN];
static __device__ unsigned g_tri[NN*TCAP];        // padded (u<<16)|v pairs
static __device__ int      g_troff[NN+1];
static __device__ unsigned g_tric[TMAX];          // compacted pairs
static __device__ float    g_V[NN];
static __device__ float    g_ent[NN];
static __device__ float    g_p[NN];
static __device__ float    g_a1[NN];
static __device__ float    g_u[NN*HH];
static __device__ float    g_z[NN*HH];
static __device__ float    g_h[NN*HH];
static __device__ float    g_sc[HH];
static __device__ float    g_sh[HH];
static __device__ float    g_gamma;
static __device__ float    g_loss;
static __device__ unsigned g_sel[NWRD];
static __device__ unsigned g_B2[NN*NWRD];
static __device__ unsigned g_B3[NN*NWRD];

// ---------------- adjacency build ----------------
__global__ void k_zero_adj() {
    int i = blockIdx.x*256 + threadIdx.x;
    if (i < NN*NWRD) g_adj[i] = 0u;
}

__global__ void k_build_adj(const int* __restrict__ ei) {
    int e = blockIdx.x*256 + threadIdx.x;
    if (e >= 32768) return;
    int u = ei[e];
    int v = ei[32768 + e];
    atomicOr(&g_adj[u*NWRD + (v>>5)], 1u << (v & 31));
}

__global__ void k_post() {
    int i = blockIdx.x*256 + threadIdx.x;
    if (i >= NN) return;
    int cnt = 0;
    for (int w = 0; w < NWRD; w++) {
        unsigned m = g_adj[i*NWRD + w];
        while (m) {
            int b = __ffs(m) - 1;
            m &= m - 1;
            if (cnt < MAXD) g_nbr[i*MAXD + cnt] = w*32 + b;
            cnt++;
        }
    }
    g_deg[i] = cnt;
}

__global__ void k_scan() {
    __shared__ int A[NN], B[NN];
    int tid = threadIdx.x;
    for (int i = tid; i < NN; i += 1024) {
        int d = g_deg[i]; if (d > MAXD) d = MAXD;
        A[i] = d;
    }
    __syncthreads();
    int* cur = A; int* nxt = B;
    for (int off = 1; off < NN; off <<= 1) {
        for (int i = tid; i < NN; i += 1024) {
            int v = cur[i];
            if (i >= off) v += cur[i-off];
            nxt[i] = v;
        }
        __syncthreads();
        int* t = cur; cur = nxt; nxt = t;
    }
    for (int i = tid; i < NN; i += 1024) g_off[i+1] = cur[i];
    if (tid == 0) { g_off[0] = 0; g_nedges = cur[NN-1]; }
}

__global__ void k_fill_edges() {
    int i = blockIdx.x*256 + threadIdx.x;
    if (i >= NN) return;
    int o = g_off[i];
    int dg = g_deg[i]; if (dg > MAXD) dg = MAXD;
    for (int t = 0; t < dg; t++)
        g_ecol[o + t] = (unsigned short)g_nbr[i*MAXD + t];
}

// ---------------- triangle pair lists (graph-static) ----------------
__global__ void k_tri() {
    int warp = (blockIdx.x*256 + threadIdx.x) >> 5;
    int lane = threadIdx.x & 31;
    if (warp >= NN) return;
    int x = warp;
    int base = g_off[x];
    int m = g_off[x+1] - base;
    int cnt = 0;
    for (int k = 0; k + 1 < m; k++) {
        unsigned u = g_ecol[base + k];
        const unsigned* rowu = &g_adj[u*NWRD];
        for (int l0 = k + 1; l0 < m; l0 += 32) {
            int l = l0 + lane;
            int ok = 0;
            unsigned v = 0;
            if (l < m) {
                v = g_ecol[base + l];
                ok = (rowu[v>>5] >> (v & 31)) & 1;
            }
            unsigned bal = __ballot_sync(0xffffffffu, ok);
            if (ok) {
                int pos = cnt + __popc(bal & ((1u << lane) - 1u));
                if (pos < TCAP) g_tri[x*TCAP + pos] = (u << 16) | v;
            }
            cnt += __popc(bal);
        }
    }
    if (lane == 0) g_tricnt[x] = cnt < TCAP ? cnt : TCAP;
}

__global__ void k_tscan() {
    __shared__ int A[NN], B[NN];
    int tid = threadIdx.x;
    for (int i = tid; i < NN; i += 1024) A[i] = g_tricnt[i];
    __syncthreads();
    int* cur = A; int* nxt = B;
    for (int off = 1; off < NN; off <<= 1) {
        for (int i = tid; i < NN; i += 1024) {
            int v = cur[i];
            if (i >= off) v += cur[i-off];
            nxt[i] = v;
        }
        __syncthreads();
        int* t = cur; cur = nxt; nxt = t;
    }
    for (int i = tid; i < NN; i += 1024) {
        int o = cur[i];
        g_troff[i+1] = o < TMAX ? o : TMAX;
    }
    if (tid == 0) g_troff[0] = 0;
}

__global__ void k_tfill() {
    int i = blockIdx.x*256 + threadIdx.x;
    if (i >= NN) return;
    int o = g_troff[i];
    int n = g_troff[i+1] - o;
    for (int t = 0; t < n; t++)
        g_tric[o + t] = g_tri[i*TCAP + t];
}

// ---------------- V (entropy pre-term) ----------------
__global__ void k_V(const float* __restrict__ x) {
    __shared__ int   snb[MAXD];
    __shared__ int   sdeg;
    __shared__ float red[DD];
    int i = blockIdx.x;
    int d = threadIdx.x;
    if (d == 0) sdeg = g_deg[i];
    __syncthreads();
    int dg = sdeg; if (dg > MAXD) dg = MAXD;
    for (int t = d; t < dg; t += DD) snb[t] = g_nbr[i*MAXD + t];
    __syncthreads();
    float xi = x[i*DD + d];
    float ax = 0.f, axx = 0.f;
    for (int t = 0; t < dg; t++) {
        float v = x[snb[t]*DD + d];
        ax  += v;
        axx += v*v;
    }
    float tt = (float)sdeg*xi*xi - 2.f*xi*ax + axx;
    red[d] = tt*tt;
    __syncthreads();
    for (int s = DD/2; s > 0; s >>= 1) {
        if (d < s) red[d] += red[d+s];
        __syncthreads();
    }
    if (d == 0) g_V[i] = sqrtf(red[0]);
}

// ---------------- per-graph softmax -> ent, gamma ----------------
__global__ void k_softmax(const int* __restrict__ batch) {
    __shared__ float sV[NN];
    __shared__ float red[1024];
    __shared__ unsigned char sB[NN];
    __shared__ float gmax[GG], gsum[GG];
    int tid = threadIdx.x;
    for (int i = tid; i < NN; i += 1024) { sV[i] = g_V[i]; sB[i] = (unsigned char)batch[i]; }
    __syncthreads();
    for (int g = 0; g < GG; g++) {
        float m = -1e30f;
        for (int i = tid; i < NN; i += 1024) if (sB[i] == g) m = fmaxf(m, sV[i]);
        red[tid] = m; __syncthreads();
        for (int s = 512; s > 0; s >>= 1) { if (tid < s) red[tid] = fmaxf(red[tid], red[tid+s]); __syncthreads(); }
        if (tid == 0) gmax[g] = red[0];
        __syncthreads();
    }
    for (int i = tid; i < NN; i += 1024) sV[i] = expf(sV[i] - gmax[sB[i]]);
    __syncthreads();
    for (int g = 0; g < GG; g++) {
        float s = 0.f;
        for (int i = tid; i < NN; i += 1024) if (sB[i] == g) s += sV[i];
        red[tid] = s; __syncthreads();
        for (int st = 512; st > 0; st >>= 1) { if (tid < st) red[tid] += red[tid+st]; __syncthreads(); }
        if (tid == 0) gsum[g] = red[0];
        __syncthreads();
    }
    float acc = 0.f;
    for (int i = tid; i < NN; i += 1024) {
        float P = sV[i] / gsum[sB[i]];
        float e = (P == 0.f) ? 0.f : -P*logf(P);
        g_ent[i] = e;
        acc += e;
    }
    red[tid] = acc; __syncthreads();
    for (int s = 512; s > 0; s >>= 1) { if (tid < s) red[tid] += red[tid+s]; __syncthreads(); }
    if (tid == 0) g_gamma = red[0];
}

// ---------------- GIN layers ----------------
__global__ void k_agg1() {
    int i = blockIdx.x*256 + threadIdx.x;
    if (i >= NN) return;
    int dg = g_deg[i]; if (dg > MAXD) dg = MAXD;
    float a = g_ent[i];
    for (int t = 0; t < dg; t++) a += g_ent[g_nbr[i*MAXD + t]];
    g_a1[i] = a;
}

__global__ void k_lin1(const float* __restrict__ w11, const float* __restrict__ b11) {
    int idx = blockIdx.x*256 + threadIdx.x;
    if (idx >= NN*HH) return;
    int i = idx >> 7, c = idx & 127;
    float v = g_a1[i]*w11[c] + b11[c];
    g_z[idx] = v > 0.f ? v : 0.f;
}

__global__ void k_bnstats(const float* __restrict__ g, const float* __restrict__ be) {
    __shared__ float red[256];
    __shared__ float mu_s;
    int c = blockIdx.x, tid = threadIdx.x;
    float s = 0.f;
    for (int r = tid; r < NN; r += 256) s += g_z[r*HH + c];
    red[tid] = s; __syncthreads();
    for (int st = 128; st > 0; st >>= 1) { if (tid < st) red[tid] += red[tid+st]; __syncthreads(); }
    if (tid == 0) mu_s = red[0] / (float)NN;
    __syncthreads();
    float mu = mu_s;
    float s2 = 0.f;
    for (int r = tid; r < NN; r += 256) { float d = g_z[r*HH + c] - mu; s2 += d*d; }
    red[tid] = s2; __syncthreads();
    for (int st = 128; st > 0; st >>= 1) { if (tid < st) red[tid] += red[tid+st]; __syncthreads(); }
    if (tid == 0) {
        float var = red[0] / (float)NN;
        float inv = 1.f / sqrtf(var + 1e-5f);
        float sc  = g[c]*inv;
        g_sc[c] = sc;
        g_sh[c] = be[c] - mu*sc;
    }
}

__global__ void k_gemm2(const float* __restrict__ W, const float* __restrict__ b) {
    __shared__ float sA[16][HH];
    int r0 = blockIdx.x*16, c = threadIdx.x;
    float scc = g_sc[c], shc = g_sh[c];
    for (int rr = 0; rr < 16; rr++)
        sA[rr][c] = g_z[(r0+rr)*HH + c]*scc + shc;
    __syncthreads();
    float acc[16];
    float bc = b[c];
    #pragma unroll
    for (int rr = 0; rr < 16; rr++) acc[rr] = bc;
    for (int k = 0; k < HH; k++) {
        float w = W[k*HH + c];
        #pragma unroll
        for (int rr = 0; rr < 16; rr++) acc[rr] += sA[rr][k]*w;
    }
    for (int rr = 0; rr < 16; rr++) g_h[(r0+rr)*HH + c] = acc[rr];
}

__global__ void k_agg() {
    __shared__ int snb[MAXD];
    __shared__ int sdeg;
    int i = blockIdx.x, f = threadIdx.x;
    if (f == 0) sdeg = g_deg[i];
    __syncthreads();
    int dg = sdeg; if (dg > MAXD) dg = MAXD;
    for (int t = f; t < dg; t += HH) snb[t] = g_nbr[i*MAXD + t];
    __syncthreads();
    float acc = g_h[i*HH + f];
    for (int t = 0; t < dg; t++) acc += g_h[snb[t]*HH + f];
    g_u[i*HH + f] = acc;
}

__global__ void k_gemm_relu(const float* __restrict__ W, const float* __restrict__ b) {
    __shared__ float sA[16][HH];
    int r0 = blockIdx.x*16, c = threadIdx.x;
    for (int rr = 0; rr < 16; rr++)
        sA[rr][c] = g_u[(r0+rr)*HH + c];
    __syncthreads();
    float acc[16];
    float bc = b[c];
    #pragma unroll
    for (int rr = 0; rr < 16; rr++) acc[rr] = bc;
    for (int k = 0; k < HH; k++) {
        float w = W[k*HH + c];
        #pragma unroll
        for (int rr = 0; rr < 16; rr++) acc[rr] += sA[rr][k]*w;
    }
    for (int rr = 0; rr < 16; rr++) {
        float v = acc[rr];
        g_z[(r0+rr)*HH + c] = v > 0.f ? v : 0.f;
    }
}

__global__ void k_final(const float* __restrict__ w32, const float* __restrict__ b32) {
    int i = blockIdx.x*256 + threadIdx.x;
    if (i >= NN) return;
    float acc = b32[0];
    for (int k = 0; k < HH; k++)
        acc += (g_z[i*HH + k]*g_sc[k] + g_sh[k]) * w32[k];
    g_p[i] = 1.f / (1.f + expf(-acc));
}

// ---------------- sort + sequential greedy (paired half-warp eval) ----------------
// Shared layout (bytes)
#define T_SKEY  0                          // NN*8
#define T_SDUM  (T_SKEY  + NN*8)           // NN*4
#define T_SENT  (T_SDUM  + NN*4)           // NN*4
#define T_SR    (T_SENT  + NN*4)           // NN*4
#define T_SOFF  (T_SR    + NN*4)           // (NN+4)*4
#define T_SEDGE (T_SOFF  + (NN+4)*4)       // 32768*2
#define T_TROFF (T_SEDGE + 32768*2)        // (NN+4)*4
#define T_TRIC  (T_TROFF + (NN+4)*4)       // TMAX*4
#define T_PARTE (T_TRIC  + TMAX*4)         // 32*8
#define T_PARTQ (T_PARTE + 32*8)           // 32*8
#define T_SSEL  (T_PARTQ + 32*8)           // NWRD*4
#define T_SDEAD (T_SSEL  + NWRD*4)         // NWRD*4
#define SMEM_BYTES (T_SDEAD + NWRD*4)

__global__ void k_sort_greedy() {
    extern __shared__ unsigned char SMB[];
    unsigned long long* skey = (unsigned long long*)(SMB + T_SKEY);
    float*  sdum  = (float*)(SMB + T_SDUM);
    float*  sent  = (float*)(SMB + T_SENT);
    float*  sr    = (float*)(SMB + T_SR);
    int*    soff  = (int*)(SMB + T_SOFF);
    unsigned short* sedge = (unsigned short*)(SMB + T_SEDGE);
    int*    stroff = (int*)(SMB + T_TROFF);
    unsigned* stric = (unsigned*)(SMB + T_TRIC);
    double* partE = (double*)(SMB + T_PARTE);
    double* partQ = (double*)(SMB + T_PARTQ);
    unsigned* ssel  = (unsigned*)(SMB + T_SSEL);
    unsigned* sdead = (unsigned*)(SMB + T_SDEAD);

    int tid = threadIdx.x;
    for (int i = tid; i < NN; i += 1024) {
        float pv = g_p[i];
        skey[i] = ((unsigned long long)(0xFFFFFFFFu - __float_as_uint(pv)) << 32) | (unsigned long long)i;
        sdum[i] = pv;
        sent[i] = g_ent[i];
    }
    for (int i = tid; i <= NN; i += 1024) { soff[i] = g_off[i]; stroff[i] = g_troff[i]; }
    {
        int nE = g_nedges;
        for (int e = tid; e < nE; e += 1024) sedge[e] = g_ecol[e];
        int nT = g_troff[NN];
        for (int e = tid; e < nT; e += 1024) stric[e] = g_tric[e];
    }
    if (tid < NWRD) {
        unsigned m = 0u;
        for (int b = 0; b < 32; b++) if (g_deg[tid*32 + b] == 0) m |= 1u << b;
        ssel[tid]  = m;   // isolated nodes pre-selected (equivalent to lazy selection)
        sdead[tid] = m;   // and ineligible
    }
    __syncthreads();

    // r_u = neighbor-sum of d (ascending neighbor order)
    for (int i = tid; i < NN; i += 1024) {
        int b = soff[i], dg = soff[i+1] - b;
        float acc = 0.f;
        for (int t = 0; t < dg; t++) acc += sdum[sedge[b + t]];
        sr[i] = acc;
    }
    __syncthreads();

    // E0, Q0 partials (double)
    {
        double e = 0.0, q = 0.0;
        for (int i = tid; i < NN; i += 1024) {
            e += (double)sent[i] * (double)sdum[i];
            q += (double)sdum[i] * (double)sr[i];
        }
        for (int o = 16; o > 0; o >>= 1) {
            e += __shfl_down_sync(0xffffffffu, e, o);
            q += __shfl_down_sync(0xffffffffu, q, o);
        }
        if ((tid & 31) == 0) { partE[tid >> 5] = e; partQ[tid >> 5] = q; }
    }
    __syncthreads();

    // bitonic sort ascending key (== descending p, ties by index ascending)
    for (int k = 2; k <= NN; k <<= 1) {
        for (int j = k >> 1; j > 0; j >>= 1) {
            for (int off = 0; off < NN; off += 1024) {
                int i = tid + off;
                int l = i ^ j;
                if (l > i) {
                    bool up = ((i & k) == 0);
                    unsigned long long a = skey[i], b = skey[l];
                    if ((a > b) == up) { skey[i] = b; skey[l] = a; }
                }
            }
            __syncthreads();
        }
    }

    if (tid >= 32) return;   // greedy runs on warp 0 only
    int lane = tid;
    int half = lane >> 4;    // 0 = candidate A, 1 = candidate B
    int gl   = lane & 15;

    double E, Q;
    {
        double ee = partE[lane], qq = partQ[lane];
        for (int o = 16; o > 0; o >>= 1) {
            ee += __shfl_down_sync(0xffffffffu, ee, o);
            qq += __shfl_down_sync(0xffffffffu, qq, o);
        }
        E = __shfl_sync(0xffffffffu, ee, 0);
        Q = __shfl_sync(0xffffffffu, qq, 0);
    }
    double gamma = (double)g_gamma;
    double lossd = gamma - E + Q;
    if (lane == 0) g_loss = (float)lossd;

    // all-lane running threshold: accept candidate ⟺ D <= thr, then thr -= D.
    double thr = 0.0;

    int t = 0;
    while (t < NN) {
        // load one 32-wide window of the sorted order; ballot eligibility once
        int pos = t + lane;
        int node = -1, elig = 0;
        if (pos < NN) {
            node = (int)(skey[pos] & 0xFFFFFFFFull);
            elig = !((sdead[node>>5] >> (node & 31)) & 1u);
        }
        unsigned bal = __ballot_sync(0xffffffffu, elig);
        t += 32;

        while (bal) {
            // A = first eligible bit (always consumed); B = second (speculative)
            int flA = __ffs(bal) - 1;
            unsigned balA = bal & (bal - 1u);      // bal minus A
            int validB = (balA != 0u);
            int flB = validB ? (__ffs(balA) - 1) : flA;
            unsigned balAB = validB ? (balA & (balA - 1u)) : balA;  // bal minus A,B

            int myfl = half ? flB : flA;
            int idx = __shfl_sync(0xffffffffu, node, myfl);

            int base = soff[idx];
            int m = soff[idx+1] - base;
            int tb = stroff[idx];
            int tn = stroff[idx+1] - tb;
            float dIf = 1.f - sdum[idx];
            float c2 = 2.f * dIf;

            // fused reduction over this half's 16 lanes:
            // red = sum_u d_u*(2*r_u + 2*dI - ent_u)  -  2*sum_pairs d_u*d_v
            float red = 0.f;
            for (int k = gl; k < m; k += 16) {
                int u = sedge[base + k];
                float du = sdum[u];
                red += du * (2.f*sr[u] + c2 - sent[u]);
            }
            for (int q = gl; q < tn; q += 16) {
                unsigned pr = stric[tb + q];
                red -= 2.f * sdum[pr >> 16] * sdum[pr & 0xFFFF];
            }
            // width-16 butterfly: all 16 lanes of each half get that candidate's total
            for (int o = 8; o > 0; o >>= 1)
                red += __shfl_xor_sync(0xffffffffu, red, o, 16);

            // each half computes its candidate's D; swap across halves once
            double dI = (double)dIf;
            double D = 2.0*dI*(double)sr[idx] - dI*(double)sent[idx] - (double)red;
            double Do = __shfl_xor_sync(0xffffffffu, D, 16);
            double DA = half ? Do : D;
            double DB = half ? D : Do;

            int accA = (DA <= thr);
            int accB = (!accA && validB && (DB <= thr));
            if (!accA && !accB) {
                bal = balAB;           // both rejected: state unchanged, ballot valid
                continue;
            }

            // commit the accepted candidate (A wins priority; B only if A rejected)
            int flAcc = accA ? flA : flB;
            thr -= accA ? DA : DB;
            // bits: A consumed always. If A accepted, B's bit stays for recheck.
            bal = accA ? balA : balAB;
            int cidx = __shfl_sync(0xffffffffu, node, flAcc);

            if (lane == 0) {
                ssel[cidx>>5]  |= 1u << (cidx & 31);
                sdead[cidx>>5] |= 1u << (cidx & 31);
            }
            int cbase = soff[cidx];
            int cm = soff[cidx+1] - cbase;
            float cdIf = 1.f - sdum[cidx];

            // delta-maintenance of sr:
            // (1) sr[nb(cidx)] += dI
            for (int k = lane; k < cm; k += 32) sr[sedge[cbase + k]] += cdIf;
            __syncwarp();
            // (2) for each u in nb(cidx) (ascending) with d_u != 0: sr[nb(u)] -= d_u
            for (int c0 = 0; c0 < cm; c0 += 32) {
                int k = c0 + lane;
                float duf = 0.f; int ub = 0, um = 0;
                if (k < cm) {
                    int u = sedge[cbase + k];
                    duf = sdum[u];
                    ub = soff[u]; um = soff[u+1] - ub;
                }
                unsigned act = __ballot_sync(0xffffffffu, duf != 0.f);
                while (act) {
                    int kk = __ffs(act) - 1; act &= act - 1;
                    float db = __shfl_sync(0xffffffffu, duf, kk);
                    int ubb = __shfl_sync(0xffffffffu, ub, kk);
                    int umb = __shfl_sync(0xffffffffu, um, kk);
                    for (int j = lane; j < umb; j += 32) sr[sedge[ubb + j]] -= db;
                    __syncwarp();
                }
            }
            // apply d update
            for (int k = lane; k < cm; k += 32) sdum[sedge[cbase + k]] = 0.f;
            if (lane == 0) sdum[cidx] = 1.f;
            // dead bits for rejected neighbors (bitwise OR — order independent)
            for (int k = lane; k < cm; k += 32) {
                int u = sedge[cbase + k];
                atomicOr(&sdead[u >> 5], 1u << (u & 31));
            }
            __syncwarp();

            // accept killed some nodes: recheck remaining window bits
            if (bal) {
                int still = ((bal >> lane) & 1u) &&
                            !((sdead[node>>5] >> (node & 31)) & 1u);
                bal = __ballot_sync(0xffffffffu, still);
            }
        }
    }
    for (int q = lane; q < NWRD; q += 32) g_sel[q] = ssel[q];
}

// ---------------- boolean adjacency powers ----------------
__global__ void k_bool(int phase) {
    __shared__ int snb[MAXD];
    __shared__ int sdeg;
    int i = blockIdx.x, w = threadIdx.x;
    if (w == 0) sdeg = g_deg[i];
    __syncthreads();
    int dg = sdeg; if (dg > MAXD) dg = MAXD;
    for (int t = w; t < dg; t += NWRD) snb[t] = g_nbr[i*MAXD + t];
    __syncthreads();
    unsigned acc = 0u;
    if (phase == 0) {
        for (int t = 0; t < dg; t++) acc |= g_adj[snb[t]*NWRD + w];
        g_B2[i*NWRD + w] = acc;
    } else {
        for (int t = 0; t < dg; t++) acc |= g_B2[snb[t]*NWRD + w];
        g_B3[i*NWRD + w] = acc;
    }
}

// ---------------- output assembly ----------------
__global__ void k_out(float* __restrict__ out, const float* __restrict__ x,
                      const int* __restrict__ batch, int out_size) {
    const int XP  = NN*DD;
    const int AE  = XP + NN*NN;
    const int SE  = AE + NN;
    const int BE  = SE + NN;
    int idx = blockIdx.x*256 + threadIdx.x;
    if (idx >= out_size) return;
    if (idx < XP) {
        int i = idx >> 8;
        bool s = (g_sel[i>>5] >> (i & 31)) & 1u;
        out[idx] = s ? x[idx] : 0.f;
    } else if (idx < AE) {
        int e = idx - XP;
        int i = e >> 11, j = e & 2047;
        unsigned b = ((g_B2[i*NWRD + (j>>5)] | g_B3[i*NWRD + (j>>5)]) >> (j & 31)) & 1u;
        bool si = (g_sel[i>>5] >> (i & 31)) & 1u;
        bool sj = (g_sel[j>>5] >> (j & 31)) & 1u;
        out[idx] = ((i != j) && b && si && sj) ? 1.f : 0.f;
    } else if (idx < SE) {
        int i = idx - AE;
        out[idx] = ((g_sel[i>>5] >> (i & 31)) & 1u) ? 1.f : 0.f;
    } else if (idx < BE) {
        int i = idx - SE;
        out[idx] = ((g_sel[i>>5] >> (i & 31)) & 1u) ? (float)batch[i] : -1.f;
    } else {
        out[idx] = g_loss;
    }
}

// ---------------- launch (with stream overlap of independent chains) ----------------
extern "C" void kernel_launch(void* const* d_in, const int* in_sizes, int n_in,
                              void* d_out, int out_size) {
    const float* x   = (const float*)d_in[0];
    const int*   ei  = (const int*)  d_in[1];
    const int*   bat = (const int*)  d_in[2];
    const float* w11 = (const float*)d_in[3];
    const float* b11 = (const float*)d_in[4];
    const float* g1  = (const float*)d_in[5];
    const float* be1 = (const float*)d_in[6];
    const float* w12 = (const float*)d_in[7];
    const float* b12 = (const float*)d_in[8];
    const float* w21 = (const float*)d_in[9];
    const float* b21 = (const float*)d_in[10];
    const float* g2  = (const float*)d_in[11];
    const float* be2 = (const float*)d_in[12];
    const float* w22 = (const float*)d_in[13];
    const float* b22 = (const float*)d_in[14];
    const float* w31 = (const float*)d_in[15];
    const float* b31 = (const float*)d_in[16];
    const float* g3  = (const float*)d_in[17];
    const float* be3 = (const float*)d_in[18];
    const float* w32 = (const float*)d_in[19];
    const float* b32 = (const float*)d_in[20];
    float* out = (float*)d_out;

    static int inited = 0;
    static cudaStream_t sTri, sBool;
    static cudaEvent_t evFork, evTriDone, evBoolDone;
    if (!inited) {
        cudaFuncSetAttribute(k_sort_greedy, cudaFuncAttributeMaxDynamicSharedMemorySize, SMEM_BYTES);
        cudaStreamCreateWithFlags(&sTri,  cudaStreamNonBlocking);
        cudaStreamCreateWithFlags(&sBool, cudaStreamNonBlocking);
        cudaEventCreateWithFlags(&evFork,     cudaEventDisableTiming);
        cudaEventCreateWithFlags(&evTriDone,  cudaEventDisableTiming);
        cudaEventCreateWithFlags(&evBoolDone, cudaEventDisableTiming);
        inited = 1;
    }

    // adjacency + CSR (default stream)
    k_zero_adj<<<(NN*NWRD + 255)/256, 256>>>();
    k_build_adj<<<(32768 + 255)/256, 256>>>(ei);
    k_post<<<NN/256, 256>>>();
    k_scan<<<1, 1024>>>();
    k_fill_edges<<<NN/256, 256>>>();

    // fork: triangles (sTri) and boolean powers (sBool) are independent of the
    // entropy/GIN chain; k_bool is also independent of the greedy kernel.
    cudaEventRecord(evFork, 0);
    cudaStreamWaitEvent(sTri,  evFork, 0);
    cudaStreamWaitEvent(sBool, evFork, 0);

    k_tri<<<NN/8, 256, 0, sTri>>>();
    k_tscan<<<1, 1024, 0, sTri>>>();
    k_tfill<<<NN/256, 256, 0, sTri>>>();
    cudaEventRecord(evTriDone, sTri);

    k_bool<<<NN, NWRD, 0, sBool>>>(0);
    k_bool<<<NN, NWRD, 0, sBool>>>(1);
    cudaEventRecord(evBoolDone, sBool);

    // entropy (default stream, overlaps with sTri/sBool)
    k_V<<<NN, DD>>>(x);
    k_softmax<<<1, 1024>>>(bat);

    // GIN layer 1
    k_agg1<<<NN/256, 256>>>();
    k_lin1<<<(NN*HH + 255)/256, 256>>>(w11, b11);
    k_bnstats<<<HH, 256>>>(g1, be1);
    k_gemm2<<<NN/16, HH>>>(w12, b12);

    // GIN layer 2
    k_agg<<<NN, HH>>>();
    k_gemm_relu<<<NN/16, HH>>>(w21, b21);
    k_bnstats<<<HH, 256>>>(g2, be2);
    k_gemm2<<<NN/16, HH>>>(w22, b22);

    // GIN layer 3
    k_agg<<<NN, HH>>>();
    k_gemm_relu<<<NN/16, HH>>>(w31, b31);
    k_bnstats<<<HH, 256>>>(g3, be3);
    k_final<<<NN/256, 256>>>(w32, b32);

    // join triangles before greedy (greedy reads g_troff/g_tric)
    cudaStreamWaitEvent(0, evTriDone, 0);
    k_sort_greedy<<<1, 1024, SMEM_BYTES>>>();

    // join boolean powers before output
    cudaStreamWaitEvent(0, evBoolDone, 0);
    k_out<<<(out_size + 255)/256, 256>>>(out, x, bat, out_size);
}

// round 16
// speedup vs baseline: 1.1142x; 1.1142x over previous
#include <cuda_runtime.h>
#include <math.h>

#define NN 2048
#define DD 256
#define HH 128
#define GG 8
#define MAXD 128
#define NWRD 64     // 32-bit words per adjacency row (2048 bits)
#define TCAP 32     // max triangle pairs per node (padded build buffer)
#define TMAX 8192   // max total compacted triangle pairs

// ---------------- device scratch (static, no runtime allocation) ----------------
static __device__ unsigned g_adj[NN*NWRD];
static __device__ int      g_deg[NN];
static __device__ int      g_nbr[NN*MAXD];
static __device__ int      g_off[NN+1];
static __device__ int      g_nedges;
static __device__ unsigned short g_ecol[32768];   // CSR columns (u16)
static __device__ int      g_tricnt[NN];
static __device__ unsigned g_tri[NN*TCAP];        // padded (u<<16)|v pairs
static __device__ int      g_troff[NN+1];
static __device__ unsigned g_tric[TMAX];          // compacted pairs
static __device__ float    g_V[NN];
static __device__ float    g_ent[NN];
static __device__ float    g_p[NN];
static __device__ float    g_a1[NN];
static __device__ float    g_u[NN*HH];
static __device__ float    g_z[NN*HH];
static __device__ float    g_h[NN*HH];
static __device__ float    g_sc[HH];
static __device__ float    g_sh[HH];
static __device__ float    g_gamma;
static __device__ float    g_loss;
static __device__ unsigned g_sel[NWRD];
static __device__ unsigned g_B2[NN*NWRD];
static __device__ unsigned g_B3[NN*NWRD];

// ---------------- adjacency build ----------------
__global__ void k_zero_adj() {
    int i = blockIdx.x*256 + threadIdx.x;
    if (i < NN*NWRD) g_adj[i] = 0u;
}

__global__ void k_build_adj(const int* __restrict__ ei) {
    int e = blockIdx.x*256 + threadIdx.x;
    if (e >= 32768) return;
    int u = ei[e];
    int v = ei[32768 + e];
    atomicOr(&g_adj[u*NWRD + (v>>5)], 1u << (v & 31));
}

__global__ void k_post() {
    int i = blockIdx.x*256 + threadIdx.x;
    if (i >= NN) return;
    int cnt = 0;
    for (int w = 0; w < NWRD; w++) {
        unsigned m = g_adj[i*NWRD + w];
        while (m) {
            int b = __ffs(m) - 1;
            m &= m - 1;
            if (cnt < MAXD) g_nbr[i*MAXD + cnt] = w*32 + b;
            cnt++;
        }
    }
    g_deg[i] = cnt;
}

__global__ void k_scan() {
    __shared__ int A[NN], B[NN];
    int tid = threadIdx.x;
    for (int i = tid; i < NN; i += 1024) {
        int d = g_deg[i]; if (d > MAXD) d = MAXD;
        A[i] = d;
    }
    __syncthreads();
    int* cur = A; int* nxt = B;
    for (int off = 1; off < NN; off <<= 1) {
        for (int i = tid; i < NN; i += 1024) {
            int v = cur[i];
            if (i >= off) v += cur[i-off];
            nxt[i] = v;
        }
        __syncthreads();
        int* t = cur; cur = nxt; nxt = t;
    }
    for (int i = tid; i < NN; i += 1024) g_off[i+1] = cur[i];
    if (tid == 0) { g_off[0] = 0; g_nedges = cur[NN-1]; }
}

__global__ void k_fill_edges() {
    int i = blockIdx.x*256 + threadIdx.x;
    if (i >= NN) return;
    int o = g_off[i];
    int dg = g_deg[i]; if (dg > MAXD) dg = MAXD;
    for (int t = 0; t < dg; t++)
        g_ecol[o + t] = (unsigned short)g_nbr[i*MAXD + t];
}

// ---------------- triangle pair lists (graph-static) ----------------
__global__ void k_tri() {
    int warp = (blockIdx.x*256 + threadIdx.x) >> 5;
    int lane = threadIdx.x & 31;
    if (warp >= NN) return;
    int x = warp;
    int base = g_off[x];
    int m = g_off[x+1] - base;
    int cnt = 0;
    for (int k = 0; k + 1 < m; k++) {
        unsigned u = g_ecol[base + k];
        const unsigned* rowu = &g_adj[u*NWRD];
        for (int l0 = k + 1; l0 < m; l0 += 32) {
            int l = l0 + lane;
            int ok = 0;
            unsigned v = 0;
            if (l < m) {
                v = g_ecol[base + l];
                ok = (rowu[v>>5] >> (v & 31)) & 1;
            }
            unsigned bal = __ballot_sync(0xffffffffu, ok);
            if (ok) {
                int pos = cnt + __popc(bal & ((1u << lane) - 1u));
                if (pos < TCAP) g_tri[x*TCAP + pos] = (u << 16) | v;
            }
            cnt += __popc(bal);
        }
    }
    if (lane == 0) g_tricnt[x] = cnt < TCAP ? cnt : TCAP;
}

__global__ void k_tscan() {
    __shared__ int A[NN], B[NN];
    int tid = threadIdx.x;
    for (int i = tid; i < NN; i += 1024) A[i] = g_tricnt[i];
    __syncthreads();
    int* cur = A; int* nxt = B;
    for (int off = 1; off < NN; off <<= 1) {
        for (int i = tid; i < NN; i += 1024) {
            int v = cur[i];
            if (i >= off) v += cur[i-off];
            nxt[i] = v;
        }
        __syncthreads();
        int* t = cur; cur = nxt; nxt = t;
    }
    for (int i = tid; i < NN; i += 1024) {
        int o = cur[i];
        g_troff[i+1] = o < TMAX ? o : TMAX;
    }
    if (tid == 0) g_troff[0] = 0;
}

__global__ void k_tfill() {
    int i = blockIdx.x*256 + threadIdx.x;
    if (i >= NN) return;
    int o = g_troff[i];
    int n = g_troff[i+1] - o;
    for (int t = 0; t < n; t++)
        g_tric[o + t] = g_tri[i*TCAP + t];
}

// ---------------- V (entropy pre-term) ----------------
__global__ void k_V(const float* __restrict__ x) {
    __shared__ int   snb[MAXD];
    __shared__ int   sdeg;
    __shared__ float red[DD];
    int i = blockIdx.x;
    int d = threadIdx.x;
    if (d == 0) sdeg = g_deg[i];
    __syncthreads();
    int dg = sdeg; if (dg > MAXD) dg = MAXD;
    for (int t = d; t < dg; t += DD) snb[t] = g_nbr[i*MAXD + t];
    __syncthreads();
    float xi = x[i*DD + d];
    float ax = 0.f, axx = 0.f;
    for (int t = 0; t < dg; t++) {
        float v = x[snb[t]*DD + d];
        ax  += v;
        axx += v*v;
    }
    float tt = (float)sdeg*xi*xi - 2.f*xi*ax + axx;
    red[d] = tt*tt;
    __syncthreads();
    for (int s = DD/2; s > 0; s >>= 1) {
        if (d < s) red[d] += red[d+s];
        __syncthreads();
    }
    if (d == 0) g_V[i] = sqrtf(red[0]);
}

// ---------------- per-graph softmax -> ent, gamma ----------------
__global__ void k_softmax(const int* __restrict__ batch) {
    __shared__ float sV[NN];
    __shared__ float red[1024];
    __shared__ unsigned char sB[NN];
    __shared__ float gmax[GG], gsum[GG];
    int tid = threadIdx.x;
    for (int i = tid; i < NN; i += 1024) { sV[i] = g_V[i]; sB[i] = (unsigned char)batch[i]; }
    __syncthreads();
    for (int g = 0; g < GG; g++) {
        float m = -1e30f;
        for (int i = tid; i < NN; i += 1024) if (sB[i] == g) m = fmaxf(m, sV[i]);
        red[tid] = m; __syncthreads();
        for (int s = 512; s > 0; s >>= 1) { if (tid < s) red[tid] = fmaxf(red[tid], red[tid+s]); __syncthreads(); }
        if (tid == 0) gmax[g] = red[0];
        __syncthreads();
    }
    for (int i = tid; i < NN; i += 1024) sV[i] = expf(sV[i] - gmax[sB[i]]);
    __syncthreads();
    for (int g = 0; g < GG; g++) {
        float s = 0.f;
        for (int i = tid; i < NN; i += 1024) if (sB[i] == g) s += sV[i];
        red[tid] = s; __syncthreads();
        for (int st = 512; st > 0; st >>= 1) { if (tid < st) red[tid] += red[tid+st]; __syncthreads(); }
        if (tid == 0) gsum[g] = red[0];
        __syncthreads();
    }
    float acc = 0.f;
    for (int i = tid; i < NN; i += 1024) {
        float P = sV[i] / gsum[sB[i]];
        float e = (P == 0.f) ? 0.f : -P*logf(P);
        g_ent[i] = e;
        acc += e;
    }
    red[tid] = acc; __syncthreads();
    for (int s = 512; s > 0; s >>= 1) { if (tid < s) red[tid] += red[tid+s]; __syncthreads(); }
    if (tid == 0) g_gamma = red[0];
}

// ---------------- GIN layers ----------------
__global__ void k_agg1() {
    int i = blockIdx.x*256 + threadIdx.x;
    if (i >= NN) return;
    int dg = g_deg[i]; if (dg > MAXD) dg = MAXD;
    float a = g_ent[i];
    for (int t = 0; t < dg; t++) a += g_ent[g_nbr[i*MAXD + t]];
    g_a1[i] = a;
}

__global__ void k_lin1(const float* __restrict__ w11, const float* __restrict__ b11) {
    int idx = blockIdx.x*256 + threadIdx.x;
    if (idx >= NN*HH) return;
    int i = idx >> 7, c = idx & 127;
    float v = g_a1[i]*w11[c] + b11[c];
    g_z[idx] = v > 0.f ? v : 0.f;
}

__global__ void k_bnstats(const float* __restrict__ g, const float* __restrict__ be) {
    __shared__ float red[256];
    __shared__ float mu_s;
    int c = blockIdx.x, tid = threadIdx.x;
    float s = 0.f;
    for (int r = tid; r < NN; r += 256) s += g_z[r*HH + c];
    red[tid] = s; __syncthreads();
    for (int st = 128; st > 0; st >>= 1) { if (tid < st) red[tid] += red[tid+st]; __syncthreads(); }
    if (tid == 0) mu_s = red[0] / (float)NN;
    __syncthreads();
    float mu = mu_s;
    float s2 = 0.f;
    for (int r = tid; r < NN; r += 256) { float d = g_z[r*HH + c] - mu; s2 += d*d; }
    red[tid] = s2; __syncthreads();
    for (int st = 128; st > 0; st >>= 1) { if (tid < st) red[tid] += red[tid+st]; __syncthreads(); }
    if (tid == 0) {
        float var = red[0] / (float)NN;
        float inv = 1.f / sqrtf(var + 1e-5f);
        float sc  = g[c]*inv;
        g_sc[c] = sc;
        g_sh[c] = be[c] - mu*sc;
    }
}

__global__ void k_gemm2(const float* __restrict__ W, const float* __restrict__ b) {
    __shared__ float sA[16][HH];
    int r0 = blockIdx.x*16, c = threadIdx.x;
    float scc = g_sc[c], shc = g_sh[c];
    for (int rr = 0; rr < 16; rr++)
        sA[rr][c] = g_z[(r0+rr)*HH + c]*scc + shc;
    __syncthreads();
    float acc[16];
    float bc = b[c];
    #pragma unroll
    for (int rr = 0; rr < 16; rr++) acc[rr] = bc;
    for (int k = 0; k < HH; k++) {
        float w = W[k*HH + c];
        #pragma unroll
        for (int rr = 0; rr < 16; rr++) acc[rr] += sA[rr][k]*w;
    }
    for (int rr = 0; rr < 16; rr++) g_h[(r0+rr)*HH + c] = acc[rr];
}

__global__ void k_agg() {
    __shared__ int snb[MAXD];
    __shared__ int sdeg;
    int i = blockIdx.x, f = threadIdx.x;
    if (f == 0) sdeg = g_deg[i];
    __syncthreads();
    int dg = sdeg; if (dg > MAXD) dg = MAXD;
    for (int t = f; t < dg; t += HH) snb[t] = g_nbr[i*MAXD + t];
    __syncthreads();
    float acc = g_h[i*HH + f];
    for (int t = 0; t < dg; t++) acc += g_h[snb[t]*HH + f];
    g_u[i*HH + f] = acc;
}

__global__ void k_gemm_relu(const float* __restrict__ W, const float* __restrict__ b) {
    __shared__ float sA[16][HH];
    int r0 = blockIdx.x*16, c = threadIdx.x;
    for (int rr = 0; rr < 16; rr++)
        sA[rr][c] = g_u[(r0+rr)*HH + c];
    __syncthreads();
    float acc[16];
    float bc = b[c];
    #pragma unroll
    for (int rr = 0; rr < 16; rr++) acc[rr] = bc;
    for (int k = 0; k < HH; k++) {
        float w = W[k*HH + c];
        #pragma unroll
        for (int rr = 0; rr < 16; rr++) acc[rr] += sA[rr][k]*w;
    }
    for (int rr = 0; rr < 16; rr++) {
        float v = acc[rr];
        g_z[(r0+rr)*HH + c] = v > 0.f ? v : 0.f;
    }
}

__global__ void k_final(const float* __restrict__ w32, const float* __restrict__ b32) {
    int i = blockIdx.x*256 + threadIdx.x;
    if (i >= NN) return;
    float acc = b32[0];
    for (int k = 0; k < HH; k++)
        acc += (g_z[i*HH + k]*g_sc[k] + g_sh[k]) * w32[k];
    g_p[i] = 1.f / (1.f + expf(-acc));
}

// ---------------- sort + sequential greedy (round-10 version, best measured) ----------------
// Shared layout (bytes)
#define T_SKEY  0                          // NN*8
#define T_SDUM  (T_SKEY  + NN*8)           // NN*4
#define T_SENT  (T_SDUM  + NN*4)           // NN*4
#define T_SR    (T_SENT  + NN*4)           // NN*4
#define T_SOFF  (T_SR    + NN*4)           // (NN+4)*4
#define T_SEDGE (T_SOFF  + (NN+4)*4)       // 32768*2
#define T_TROFF (T_SEDGE + 32768*2)        // (NN+4)*4
#define T_TRIC  (T_TROFF + (NN+4)*4)       // TMAX*4
#define T_PARTE (T_TRIC  + TMAX*4)         // 32*8
#define T_PARTQ (T_PARTE + 32*8)           // 32*8
#define T_SSEL  (T_PARTQ + 32*8)           // NWRD*4
#define T_SREJ  (T_SSEL  + NWRD*4)
#define SMEM_BYTES (T_SREJ + NWRD*4)

__global__ void k_sort_greedy() {
    extern __shared__ unsigned char SMB[];
    unsigned long long* skey = (unsigned long long*)(SMB + T_SKEY);
    float*  sdum  = (float*)(SMB + T_SDUM);
    float*  sent  = (float*)(SMB + T_SENT);
    float*  sr    = (float*)(SMB + T_SR);
    int*    soff  = (int*)(SMB + T_SOFF);
    unsigned short* sedge = (unsigned short*)(SMB + T_SEDGE);
    int*    stroff = (int*)(SMB + T_TROFF);
    unsigned* stric = (unsigned*)(SMB + T_TRIC);
    double* partE = (double*)(SMB + T_PARTE);
    double* partQ = (double*)(SMB + T_PARTQ);
    unsigned* ssel = (unsigned*)(SMB + T_SSEL);
    unsigned* srej = (unsigned*)(SMB + T_SREJ);

    int tid = threadIdx.x;
    for (int i = tid; i < NN; i += 1024) {
        float pv = g_p[i];
        skey[i] = ((unsigned long long)(0xFFFFFFFFu - __float_as_uint(pv)) << 32) | (unsigned long long)i;
        sdum[i] = pv;
        sent[i] = g_ent[i];
    }
    for (int i = tid; i <= NN; i += 1024) { soff[i] = g_off[i]; stroff[i] = g_troff[i]; }
    {
        int nE = g_nedges;
        for (int e = tid; e < nE; e += 1024) sedge[e] = g_ecol[e];
        int nT = g_troff[NN];
        for (int e = tid; e < nT; e += 1024) stric[e] = g_tric[e];
    }
    if (tid < NWRD) {
        srej[tid] = 0u;
        unsigned m = 0u;
        for (int b = 0; b < 32; b++) if (g_deg[tid*32 + b] == 0) m |= 1u << b;
        ssel[tid] = m;   // isolated nodes pre-selected (equivalent to lazy selection)
    }
    __syncthreads();

    // r_u = neighbor-sum of d (ascending neighbor order)
    for (int i = tid; i < NN; i += 1024) {
        int b = soff[i], dg = soff[i+1] - b;
        float acc = 0.f;
        for (int t = 0; t < dg; t++) acc += sdum[sedge[b + t]];
        sr[i] = acc;
    }
    __syncthreads();

    // E0, Q0 partials (double)
    {
        double e = 0.0, q = 0.0;
        for (int i = tid; i < NN; i += 1024) {
            e += (double)sent[i] * (double)sdum[i];
            q += (double)sdum[i] * (double)sr[i];
        }
        for (int o = 16; o > 0; o >>= 1) {
            e += __shfl_down_sync(0xffffffffu, e, o);
            q += __shfl_down_sync(0xffffffffu, q, o);
        }
        if ((tid & 31) == 0) { partE[tid >> 5] = e; partQ[tid >> 5] = q; }
    }
    __syncthreads();

    // bitonic sort ascending key (== descending p, ties by index ascending)
    for (int k = 2; k <= NN; k <<= 1) {
        for (int j = k >> 1; j > 0; j >>= 1) {
            for (int off = 0; off < NN; off += 1024) {
                int i = tid + off;
                int l = i ^ j;
                if (l > i) {
                    bool up = ((i & k) == 0);
                    unsigned long long a = skey[i], b = skey[l];
                    if ((a > b) == up) { skey[i] = b; skey[l] = a; }
                }
            }
            __syncthreads();
        }
    }

    if (tid >= 32) return;   // greedy runs on warp 0 only
    int lane = tid;

    double E, Q;
    {
        double ee = partE[lane], qq = partQ[lane];
        for (int o = 16; o > 0; o >>= 1) {
            ee += __shfl_down_sync(0xffffffffu, ee, o);
            qq += __shfl_down_sync(0xffffffffu, qq, o);
        }
        E = __shfl_sync(0xffffffffu, ee, 0);
        Q = __shfl_sync(0xffffffffu, qq, 0);
    }
    double gamma = (double)g_gamma;
    double lossd = gamma - E + Q;
    if (lane == 0) g_loss = (float)lossd;

    // lane-0 running threshold: accept candidate ⟺ D <= thr, then thr -= D.
    double thr = 0.0;

    int t = 0;
    while (t < NN) {
        // warp-parallel candidate scan: 32-wide window, first eligible wins
        int pos = t + lane;
        int node = -1, elig = 0;
        if (pos < NN) {
            node = (int)(skey[pos] & 0xFFFFFFFFull);
            elig = !(((ssel[node>>5] | srej[node>>5]) >> (node & 31)) & 1u);
        }
        unsigned bal = __ballot_sync(0xffffffffu, elig);
        if (!bal) { t += 32; continue; }
        int fl = __ffs(bal) - 1;
        int idx = __shfl_sync(0xffffffffu, node, fl);
        t += fl + 1;

        int base = soff[idx];
        int m = soff[idx+1] - base;
        int tb = stroff[idx];
        int tn = stroff[idx+1] - tb;
        float dIf = 1.f - sdum[idx];
        float c2 = 2.f * dIf;

        // fused single reduction:
        // red = sum_u d_u*(2*r_u + 2*dI - ent_u)  -  2*sum_pairs d_u*d_v
        float red = 0.f;
        for (int k = lane; k < m; k += 32) {
            int u = sedge[base + k];
            float du = sdum[u];
            red += du * (2.f*sr[u] + c2 - sent[u]);
        }
        for (int q = lane; q < tn; q += 32) {
            unsigned pr = stric[tb + q];
            red -= 2.f * sdum[pr >> 16] * sdum[pr & 0xFFFF];
        }
        for (int o = 16; o > 0; o >>= 1)
            red += __shfl_down_sync(0xffffffffu, red, o);

        int accept = 0;
        if (lane == 0) {
            double dI = (double)dIf;
            double D = 2.0*dI*(double)sr[idx] - dI*(double)sent[idx] - (double)red;
            if (D <= thr) { accept = 1; thr -= D; }
        }
        accept = __shfl_sync(0xffffffffu, accept, 0);
        if (!accept) continue;

        if (lane == 0) ssel[idx>>5] |= 1u << (idx & 31);

        // delta-maintenance of sr:
        // (1) sr[nb(idx)] += dI
        for (int k = lane; k < m; k += 32) sr[sedge[base + k]] += dIf;
        __syncwarp();
        // (2) for each u in nb(idx) (ascending) with d_u != 0: sr[nb(u)] -= d_u
        for (int c0 = 0; c0 < m; c0 += 32) {
            int k = c0 + lane;
            float duf = 0.f; int ub = 0, um = 0;
            if (k < m) {
                int u = sedge[base + k];
                duf = sdum[u];
                ub = soff[u]; um = soff[u+1] - ub;
            }
            unsigned act = __ballot_sync(0xffffffffu, duf != 0.f);
            while (act) {
                int kk = __ffs(act) - 1; act &= act - 1;
                float db = __shfl_sync(0xffffffffu, duf, kk);
                int ubb = __shfl_sync(0xffffffffu, ub, kk);
                int umb = __shfl_sync(0xffffffffu, um, kk);
                for (int j = lane; j < umb; j += 32) sr[sedge[ubb + j]] -= db;
                __syncwarp();
            }
        }
        // apply d update
        for (int k = lane; k < m; k += 32) sdum[sedge[base + k]] = 0.f;
        if (lane == 0) sdum[idx] = 1.f;
        // rejection bits from neighbor list (bitwise OR — order independent)
        for (int k = lane; k < m; k += 32) {
            int u = sedge[base + k];
            atomicOr(&srej[u >> 5], 1u << (u & 31));
        }
        __syncwarp();
    }
    for (int q = lane; q < NWRD; q += 32) g_sel[q] = ssel[q];
}

// ---------------- boolean adjacency powers ----------------
__global__ void k_bool(int phase) {
    __shared__ int snb[MAXD];
    __shared__ int sdeg;
    int i = blockIdx.x, w = threadIdx.x;
    if (w == 0) sdeg = g_deg[i];
    __syncthreads();
    int dg = sdeg; if (dg > MAXD) dg = MAXD;
    for (int t = w; t < dg; t += NWRD) snb[t] = g_nbr[i*MAXD + t];
    __syncthreads();
    unsigned acc = 0u;
    if (phase == 0) {
        for (int t = 0; t < dg; t++) acc |= g_adj[snb[t]*NWRD + w];
        g_B2[i*NWRD + w] = acc;
    } else {
        for (int t = 0; t < dg; t++) acc |= g_B2[snb[t]*NWRD + w];
        g_B3[i*NWRD + w] = acc;
    }
}

// ---------------- output assembly ----------------
__global__ void k_out(float* __restrict__ out, const float* __restrict__ x,
                      const int* __restrict__ batch, int out_size) {
    const int XP  = NN*DD;
    const int AE  = XP + NN*NN;
    const int SE  = AE + NN;
    const int BE  = SE + NN;
    int idx = blockIdx.x*256 + threadIdx.x;
    if (idx >= out_size) return;
    if (idx < XP) {
        int i = idx >> 8;
        bool s = (g_sel[i>>5] >> (i & 31)) & 1u;
        out[idx] = s ? x[idx] : 0.f;
    } else if (idx < AE) {
        int e = idx - XP;
        int i = e >> 11, j = e & 2047;
        unsigned b = ((g_B2[i*NWRD + (j>>5)] | g_B3[i*NWRD + (j>>5)]) >> (j & 31)) & 1u;
        bool si = (g_sel[i>>5] >> (i & 31)) & 1u;
        bool sj = (g_sel[j>>5] >> (j & 31)) & 1u;
        out[idx] = ((i != j) && b && si && sj) ? 1.f : 0.f;
    } else if (idx < SE) {
        int i = idx - AE;
        out[idx] = ((g_sel[i>>5] >> (i & 31)) & 1u) ? 1.f : 0.f;
    } else if (idx < BE) {
        int i = idx - SE;
        out[idx] = ((g_sel[i>>5] >> (i & 31)) & 1u) ? (float)batch[i] : -1.f;
    } else {
        out[idx] = g_loss;
    }
}

// ---------------- launch (with stream overlap of independent chains) ----------------
extern "C" void kernel_launch(void* const* d_in, const int* in_sizes, int n_in,
                              void* d_out, int out_size) {
    const float* x   = (const float*)d_in[0];
    const int*   ei  = (const int*)  d_in[1];
    const int*   bat = (const int*)  d_in[2];
    const float* w11 = (const float*)d_in[3];
    const float* b11 = (const float*)d_in[4];
    const float* g1  = (const float*)d_in[5];
    const float* be1 = (const float*)d_in[6];
    const float* w12 = (const float*)d_in[7];
    const float* b12 = (const float*)d_in[8];
    const float* w21 = (const float*)d_in[9];
    const float* b21 = (const float*)d_in[10];
    const float* g2  = (const float*)d_in[11];
    const float* be2 = (const float*)d_in[12];
    const float* w22 = (const float*)d_in[13];
    const float* b22 = (const float*)d_in[14];
    const float* w31 = (const float*)d_in[15];
    const float* b31 = (const float*)d_in[16];
    const float* g3  = (const float*)d_in[17];
    const float* be3 = (const float*)d_in[18];
    const float* w32 = (const float*)d_in[19];
    const float* b32 = (const float*)d_in[20];
    float* out = (float*)d_out;

    static int inited = 0;
    static cudaStream_t sTri, sBool;
    static cudaEvent_t evFork, evTriDone, evBoolDone;
    if (!inited) {
        cudaFuncSetAttribute(k_sort_greedy, cudaFuncAttributeMaxDynamicSharedMemorySize, SMEM_BYTES);
        cudaStreamCreateWithFlags(&sTri,  cudaStreamNonBlocking);
        cudaStreamCreateWithFlags(&sBool, cudaStreamNonBlocking);
        cudaEventCreateWithFlags(&evFork,     cudaEventDisableTiming);
        cudaEventCreateWithFlags(&evTriDone,  cudaEventDisableTiming);
        cudaEventCreateWithFlags(&evBoolDone, cudaEventDisableTiming);
        inited = 1;
    }

    // adjacency + CSR (default stream)
    k_zero_adj<<<(NN*NWRD + 255)/256, 256>>>();
    k_build_adj<<<(32768 + 255)/256, 256>>>(ei);
    k_post<<<NN/256, 256>>>();
    k_scan<<<1, 1024>>>();
    k_fill_edges<<<NN/256, 256>>>();

    // fork: triangles (sTri) and boolean powers (sBool) are independent of the
    // entropy/GIN chain; k_bool is also independent of the greedy kernel.
    cudaEventRecord(evFork, 0);
    cudaStreamWaitEvent(sTri,  evFork, 0);
    cudaStreamWaitEvent(sBool, evFork, 0);

    k_tri<<<NN/8, 256, 0, sTri>>>();
    k_tscan<<<1, 1024, 0, sTri>>>();
    k_tfill<<<NN/256, 256, 0, sTri>>>();
    cudaEventRecord(evTriDone, sTri);

    k_bool<<<NN, NWRD, 0, sBool>>>(0);
    k_bool<<<NN, NWRD, 0, sBool>>>(1);
    cudaEventRecord(evBoolDone, sBool);

    // entropy (default stream, overlaps with sTri/sBool)
    k_V<<<NN, DD>>>(x);
    k_softmax<<<1, 1024>>>(bat);

    // GIN layer 1
    k_agg1<<<NN/256, 256>>>();
    k_lin1<<<(NN*HH + 255)/256, 256>>>(w11, b11);
    k_bnstats<<<HH, 256>>>(g1, be1);
    k_gemm2<<<NN/16, HH>>>(w12, b12);

    // GIN layer 2
    k_agg<<<NN, HH>>>();
    k_gemm_relu<<<NN/16, HH>>>(w21, b21);
    k_bnstats<<<HH, 256>>>(g2, be2);
    k_gemm2<<<NN/16, HH>>>(w22, b22);

    // GIN layer 3
    k_agg<<<NN, HH>>>();
    k_gemm_relu<<<NN/16, HH>>>(w31, b31);
    k_bnstats<<<HH, 256>>>(g3, be3);
    k_final<<<NN/256, 256>>>(w32, b32);

    // join triangles before greedy (greedy reads g_troff/g_tric)
    cudaStreamWaitEvent(0, evTriDone, 0);
    k_sort_greedy<<<1, 1024, SMEM_BYTES>>>();

    // join boolean powers before output
    cudaStreamWaitEvent(0, evBoolDone, 0);
    k_out<<<(out_size + 255)/256, 256>>>(out, x, bat, out_size);
}